// round 4
// baseline (speedup 1.0000x reference)
#include <cuda_runtime.h>
#include <cuda_fp16.h>
#include <math.h>

#define NMAX   50000
#define EMAX   400000
#define D      64
#define DD     128
#define NBND   64
#define NROWS  65

// Device scratch
__device__ __align__(16) float   g_acc[NMAX * DD];     // per-dst scaled cat accum [N,128]
__device__ float  g_accs[NMAX];                        // per-dst sum of scales
__device__ int    g_din[NMAX];
__device__ int    g_dout[NMAX];
__device__ __align__(16) __half2 g_feath[NMAX * 32];   // fp16 copy of feat [N,64]
__device__ __align__(16) __half  g_t2h[NROWS * D];     // fp16 (embed @ G_w.T) [65,64]

__device__ __forceinline__ void red_add_v4(float* p, float4 v) {
    asm volatile("red.global.add.v4.f32 [%0], {%1, %2, %3, %4};"
                 :: "l"(p), "f"(v.x), "f"(v.y), "f"(v.z), "f"(v.w)
                 : "memory");
}

__device__ __forceinline__ void fmaf2(unsigned long long& c,
                                      unsigned long long a,
                                      unsigned long long b) {
    asm("fma.rn.f32x2 %0, %1, %2, %0;" : "+l"(c) : "l"(a), "l"(b));
}

// accumulate elementwise product of 8 halves x 8 halves into 8 fp32 accumulators
__device__ __forceinline__ void acc_prod(uint4 tv, uint4 fv, float4& ca, float4& cb) {
    const __half2* th = (const __half2*)&tv;
    const __half2* fh = (const __half2*)&fv;
    float2 t0 = __half22float2(th[0]), f0 = __half22float2(fh[0]);
    float2 t1 = __half22float2(th[1]), f1 = __half22float2(fh[1]);
    float2 t2 = __half22float2(th[2]), f2 = __half22float2(fh[2]);
    float2 t3 = __half22float2(th[3]), f3 = __half22float2(fh[3]);
    ca.x = fmaf(t0.x, f0.x, ca.x); ca.y = fmaf(t0.y, f0.y, ca.y);
    ca.z = fmaf(t1.x, f1.x, ca.z); ca.w = fmaf(t1.y, f1.y, ca.w);
    cb.x = fmaf(t2.x, f2.x, cb.x); cb.y = fmaf(t2.y, f2.y, cb.y);
    cb.z = fmaf(t3.x, f3.x, cb.z); cb.w = fmaf(t3.y, f3.y, cb.w);
}

// ---------------------------------------------------------------------------
// 0) zero scratch + convert feat -> fp16
__global__ void prep_kernel(const float* __restrict__ feat, int n) {
    int i = blockIdx.x * blockDim.x + threadIdx.x;
    int stride = gridDim.x * blockDim.x;
    int tot4 = n * (DD / 4);
    float4 z = make_float4(0.f, 0.f, 0.f, 0.f);
    for (int k = i; k < tot4; k += stride) ((float4*)g_acc)[k] = z;
    int toth = n * 32;  // half2 count
    for (int k = i; k < toth; k += stride) {
        float2 v = ((const float2*)feat)[k];
        g_feath[k] = __floats2half2_rn(v.x, v.y);
    }
    for (int k = i; k < n; k += stride) {
        g_accs[k] = 0.f;
        g_din[k]  = 0;
        g_dout[k] = 0;
    }
}

// ---------------------------------------------------------------------------
// 1) t2h = fp16(embed_table @ G_w.T)
__global__ void table2_kernel(const float* __restrict__ embed,
                              const float* __restrict__ Gw) {
    int t = blockIdx.x * blockDim.x + threadIdx.x;
    if (t >= NROWS * D) return;
    int r = t >> 6;
    int d = t & 63;
    float s = 0.f;
#pragma unroll
    for (int k = 0; k < 32; k++)
        s = fmaf(embed[r * 32 + k], Gw[d * 32 + k], s);
    g_t2h[t] = __float2half_rn(s);
}

// ---------------------------------------------------------------------------
// 2) degrees
__global__ void degree_kernel(const int* __restrict__ src,
                              const int* __restrict__ dst, int e) {
    int i = blockIdx.x * blockDim.x + threadIdx.x;
    if (i < e) {
        atomicAdd(&g_din[dst[i]], 1);
        atomicAdd(&g_dout[src[i]], 1);
    }
}

// ---------------------------------------------------------------------------
// 3) edge kernel: 8 lanes per edge (4 edges per warp), fp16 gathers, fp32 math.
__global__ void edge_kernel(const float2* __restrict__ loc,
                            const float* __restrict__ bnd,
                            const int* __restrict__ src,
                            const int* __restrict__ dst,
                            const int* __restrict__ inter,
                            int e) {
    __shared__ float sb[NBND];
    if (threadIdx.x < NBND) sb[threadIdx.x] = bnd[threadIdx.x];
    __syncthreads();

    int gtid  = blockIdx.x * blockDim.x + threadIdx.x;
    int eidx0 = gtid >> 3;          // one edge per 8 threads
    int sub   = threadIdx.x & 7;
    int lane  = threadIdx.x & 31;
    int base  = lane & 24;          // first lane of this 8-group

    bool valid = (eidx0 < e);
    int eidx = valid ? eidx0 : 0;

    int s = src[eidx];
    int d = dst[eidx];
    float2 ls = loc[s];

    int id = 0;
    if (sub >= 1 && sub <= 5) id = inter[eidx * 5 + (sub - 1)];

    int bk = 0;
    if (sub < 6) {
        float2 o = (sub == 0) ? loc[d] : loc[id];
        float dx = o.x - ls.x;
        float dy = o.y - ls.y;
        float v = sqrtf(dx * dx + dy * dy);
        int lo = 0, hi = NBND;
        while (lo < hi) {
            int mid = (lo + hi) >> 1;
            if (sb[mid] < v) lo = mid + 1; else hi = mid;
        }
        bk = lo;
    }

    const unsigned FULL = 0xffffffffu;
    const uint4* t4 = (const uint4*)g_t2h;     // 8 halves per uint4, row = 8 uint4
    const uint4* f4 = (const uint4*)g_feath;

    // part 1: dist_embed1 * feat[src]
    int b1 = __shfl_sync(FULL, bk, base);
    float4 c0a = make_float4(0.f, 0.f, 0.f, 0.f);
    float4 c0b = make_float4(0.f, 0.f, 0.f, 0.f);
    acc_prod(t4[b1 * 8 + sub], f4[s * 8 + sub], c0a, c0b);

    // part 2: sum_j dist_embed_j * feat[inter_j]
    float4 c1a = make_float4(0.f, 0.f, 0.f, 0.f);
    float4 c1b = make_float4(0.f, 0.f, 0.f, 0.f);
#pragma unroll
    for (int j = 1; j <= 5; j++) {
        int bj = __shfl_sync(FULL, bk, base + j);
        int ij = __shfl_sync(FULL, id, base + j);
        acc_prod(t4[bj * 8 + sub], f4[ij * 8 + sub], c1a, c1b);
    }

    float sc = rsqrtf(fmaxf((float)g_din[d], 1.f)) *
               rsqrtf(fmaxf((float)g_dout[s], 1.f));
    float m = 0.2f * sc;
    c0a.x *= sc; c0a.y *= sc; c0a.z *= sc; c0a.w *= sc;
    c0b.x *= sc; c0b.y *= sc; c0b.z *= sc; c0b.w *= sc;
    c1a.x *= m;  c1a.y *= m;  c1a.z *= m;  c1a.w *= m;
    c1b.x *= m;  c1b.y *= m;  c1b.z *= m;  c1b.w *= m;

    if (valid) {
        float* p0 = g_acc + d * DD + sub * 8;   // dims [8*sub .. 8*sub+7]
        red_add_v4(p0,          c0a);
        red_add_v4(p0 + 4,      c0b);
        red_add_v4(p0 + D,      c1a);
        red_add_v4(p0 + D + 4,  c1b);
        if (sub == 0) atomicAdd(&g_accs[d], sc);
    }
}

// ---------------------------------------------------------------------------
// 4) persistent GEMM: out = acc @ W^T + accs*b, fma.f32x2 packed over k-pairs.
//    W staged once per block: Ws[d][k] with k-stride KP (conflict-free LDS.64).
#define KP 130
__global__ void gemm_kernel(const float* __restrict__ aggw,
                            const float* __restrict__ aggb,
                            float* __restrict__ out, int n) {
    __shared__ float Ws[D * KP];     // 33.3 KB
    __shared__ float As[16 * KP];    // 8.3 KB
    __shared__ float Ss[16];
    __shared__ float Bs[D];

    int tid = threadIdx.x;
    for (int idx = tid; idx < D * DD; idx += 256) {
        int dd = idx >> 7;
        int k  = idx & 127;
        Ws[dd * KP + k] = aggw[idx];
    }
    if (tid < D) Bs[tid] = aggb[tid];

    int ntiles = (n + 15) >> 4;
    int w = tid >> 5;
    int l = tid & 31;

    for (int t = blockIdx.x; t < ntiles; t += gridDim.x) {
        int basev = t << 4;
        __syncthreads();
        // stage 16 acc rows (8B-aligned stores; row stride KP*4 = 520B)
        for (int idx = tid; idx < 16 * 32; idx += 256) {
            int j = idx >> 5;
            int c = idx & 31;
            int node = basev + j;
            float4 v = make_float4(0.f, 0.f, 0.f, 0.f);
            if (node < n) v = ((const float4*)g_acc)[node * 32 + c];
            float* p = As + j * KP + c * 4;
            *(float2*)p       = make_float2(v.x, v.y);
            *(float2*)(p + 2) = make_float2(v.z, v.w);
        }
        if (tid < 16) Ss[tid] = (basev + tid < n) ? g_accs[basev + tid] : 0.f;
        __syncthreads();

        const float* ar0 = As + (2 * w) * KP;
        const float* ar1 = As + (2 * w + 1) * KP;
        const float* wr0 = Ws + l * KP;
        const float* wr1 = Ws + (l + 32) * KP;

        unsigned long long acc00 = 0ull, acc01 = 0ull, acc10 = 0ull, acc11 = 0ull;
#pragma unroll 8
        for (int k = 0; k < DD; k += 2) {
            unsigned long long a0 = *(const unsigned long long*)(ar0 + k);
            unsigned long long a1 = *(const unsigned long long*)(ar1 + k);
            unsigned long long w0 = *(const unsigned long long*)(wr0 + k);
            unsigned long long w1 = *(const unsigned long long*)(wr1 + k);
            fmaf2(acc00, a0, w0);
            fmaf2(acc01, a0, w1);
            fmaf2(acc10, a1, w0);
            fmaf2(acc11, a1, w1);
        }

        float2 p00 = *(float2*)&acc00;
        float2 p01 = *(float2*)&acc01;
        float2 p10 = *(float2*)&acc10;
        float2 p11 = *(float2*)&acc11;

        int n0 = basev + 2 * w;
        int n1 = n0 + 1;
        if (n0 < n) {
            float ss = Ss[2 * w];
            out[n0 * D + l]      = (p00.x + p00.y) + ss * Bs[l];
            out[n0 * D + l + 32] = (p01.x + p01.y) + ss * Bs[l + 32];
        }
        if (n1 < n) {
            float ss = Ss[2 * w + 1];
            out[n1 * D + l]      = (p10.x + p10.y) + ss * Bs[l];
            out[n1 * D + l + 32] = (p11.x + p11.y) + ss * Bs[l + 32];
        }
    }
}

// ---------------------------------------------------------------------------
extern "C" void kernel_launch(void* const* d_in, const int* in_sizes, int n_in,
                              void* d_out, int out_size) {
    const float*  feat  = (const float*)d_in[0];
    const float2* loc   = (const float2*)d_in[1];
    const float*  embed = (const float*)d_in[2];
    const float*  Gw    = (const float*)d_in[3];
    const float*  aggw  = (const float*)d_in[4];
    const float*  aggb  = (const float*)d_in[5];
    const float*  bnd   = (const float*)d_in[6];
    const int*    src   = (const int*)d_in[7];
    const int*    dst   = (const int*)d_in[8];
    const int*    inter = (const int*)d_in[9];
    float* out = (float*)d_out;

    int n = in_sizes[0] / D;   // 50000
    int e = in_sizes[7];       // 400000

    prep_kernel<<<2048, 256>>>(feat, n);
    table2_kernel<<<(NROWS * D + 255) / 256, 256>>>(embed, Gw);
    degree_kernel<<<(e + 255) / 256, 256>>>(src, dst, e);

    long long threads_needed = (long long)e * 8;
    int blocks = (int)((threads_needed + 255) / 256);
    edge_kernel<<<blocks, 256>>>(loc, bnd, src, dst, inter, e);

    gemm_kernel<<<740, 256>>>(aggw, aggb, out, n);
}

// round 5
// speedup vs baseline: 1.0016x; 1.0016x over previous
#include <cuda_runtime.h>
#include <cuda_fp16.h>
#include <math.h>

#define NMAX   50000
#define EMAX   400000
#define D      64
#define DD     128
#define NBND   64
#define NROWS  65

// Device scratch
__device__ __align__(16) float   g_acc[NMAX * DD];     // per-dst scaled cat accum [N,128]
__device__ float  g_accs[NMAX];                        // per-dst sum of scales
__device__ int    g_din[NMAX];
__device__ int    g_dout[NMAX];
__device__ __align__(16) __half2 g_feath[NMAX * 32];   // fp16 copy of feat [N,64]
__device__ __align__(16) __half  g_t2h[NROWS * D];     // fp16 (embed @ G_w.T) [65,64]

__device__ __forceinline__ void red_add_v4(float* p, float4 v) {
    asm volatile("red.global.add.v4.f32 [%0], {%1, %2, %3, %4};"
                 :: "l"(p), "f"(v.x), "f"(v.y), "f"(v.z), "f"(v.w)
                 : "memory");
}

__device__ __forceinline__ void fmaf2(unsigned long long& c,
                                      unsigned long long a,
                                      unsigned long long b) {
    asm("fma.rn.f32x2 %0, %1, %2, %0;" : "+l"(c) : "l"(a), "l"(b));
}

// accumulate elementwise product of 8 halves x 8 halves into 8 fp32 accumulators
__device__ __forceinline__ void acc_prod(uint4 tv, uint4 fv, float4& ca, float4& cb) {
    const __half2* th = (const __half2*)&tv;
    const __half2* fh = (const __half2*)&fv;
    float2 t0 = __half22float2(th[0]), f0 = __half22float2(fh[0]);
    float2 t1 = __half22float2(th[1]), f1 = __half22float2(fh[1]);
    float2 t2 = __half22float2(th[2]), f2 = __half22float2(fh[2]);
    float2 t3 = __half22float2(th[3]), f3 = __half22float2(fh[3]);
    ca.x = fmaf(t0.x, f0.x, ca.x); ca.y = fmaf(t0.y, f0.y, ca.y);
    ca.z = fmaf(t1.x, f1.x, ca.z); ca.w = fmaf(t1.y, f1.y, ca.w);
    cb.x = fmaf(t2.x, f2.x, cb.x); cb.y = fmaf(t2.y, f2.y, cb.y);
    cb.z = fmaf(t3.x, f3.x, cb.z); cb.w = fmaf(t3.y, f3.y, cb.w);
}

// ---------------------------------------------------------------------------
// 0) zero scratch + convert feat -> fp16
__global__ void prep_kernel(const float* __restrict__ feat, int n) {
    int i = blockIdx.x * blockDim.x + threadIdx.x;
    int stride = gridDim.x * blockDim.x;
    int tot4 = n * (DD / 4);
    float4 z = make_float4(0.f, 0.f, 0.f, 0.f);
    for (int k = i; k < tot4; k += stride) ((float4*)g_acc)[k] = z;
    int toth = n * 32;  // half2 count
    for (int k = i; k < toth; k += stride) {
        float2 v = ((const float2*)feat)[k];
        g_feath[k] = __floats2half2_rn(v.x, v.y);
    }
    for (int k = i; k < n; k += stride) {
        g_accs[k] = 0.f;
        g_din[k]  = 0;
        g_dout[k] = 0;
    }
}

// ---------------------------------------------------------------------------
// 1) t2h = fp16(embed_table @ G_w.T)
__global__ void table2_kernel(const float* __restrict__ embed,
                              const float* __restrict__ Gw) {
    int t = blockIdx.x * blockDim.x + threadIdx.x;
    if (t >= NROWS * D) return;
    int r = t >> 6;
    int d = t & 63;
    float s = 0.f;
#pragma unroll
    for (int k = 0; k < 32; k++)
        s = fmaf(embed[r * 32 + k], Gw[d * 32 + k], s);
    g_t2h[t] = __float2half_rn(s);
}

// ---------------------------------------------------------------------------
// 2) degrees
__global__ void degree_kernel(const int* __restrict__ src,
                              const int* __restrict__ dst, int e) {
    int i = blockIdx.x * blockDim.x + threadIdx.x;
    if (i < e) {
        atomicAdd(&g_din[dst[i]], 1);
        atomicAdd(&g_dout[src[i]], 1);
    }
}

// ---------------------------------------------------------------------------
// 3) edge kernel: 8 lanes per edge (4 edges per warp), fp16 gathers, fp32 math.
__global__ void edge_kernel(const float2* __restrict__ loc,
                            const float* __restrict__ bnd,
                            const int* __restrict__ src,
                            const int* __restrict__ dst,
                            const int* __restrict__ inter,
                            int e) {
    __shared__ float sb[NBND];
    if (threadIdx.x < NBND) sb[threadIdx.x] = bnd[threadIdx.x];
    __syncthreads();

    int gtid  = blockIdx.x * blockDim.x + threadIdx.x;
    int eidx0 = gtid >> 3;          // one edge per 8 threads
    int sub   = threadIdx.x & 7;
    int lane  = threadIdx.x & 31;
    int base  = lane & 24;          // first lane of this 8-group

    bool valid = (eidx0 < e);
    int eidx = valid ? eidx0 : 0;

    int s = src[eidx];
    int d = dst[eidx];
    float2 ls = loc[s];

    int id = 0;
    if (sub >= 1 && sub <= 5) id = inter[eidx * 5 + (sub - 1)];

    int bk = 0;
    if (sub < 6) {
        float2 o = (sub == 0) ? loc[d] : loc[id];
        float dx = o.x - ls.x;
        float dy = o.y - ls.y;
        float v = sqrtf(dx * dx + dy * dy);
        int lo = 0, hi = NBND;
        while (lo < hi) {
            int mid = (lo + hi) >> 1;
            if (sb[mid] < v) lo = mid + 1; else hi = mid;
        }
        bk = lo;
    }

    const unsigned FULL = 0xffffffffu;
    const uint4* t4 = (const uint4*)g_t2h;     // 8 halves per uint4, row = 8 uint4
    const uint4* f4 = (const uint4*)g_feath;

    // part 1: dist_embed1 * feat[src]
    int b1 = __shfl_sync(FULL, bk, base);
    float4 c0a = make_float4(0.f, 0.f, 0.f, 0.f);
    float4 c0b = make_float4(0.f, 0.f, 0.f, 0.f);
    acc_prod(t4[b1 * 8 + sub], f4[s * 8 + sub], c0a, c0b);

    // part 2: sum_j dist_embed_j * feat[inter_j]
    float4 c1a = make_float4(0.f, 0.f, 0.f, 0.f);
    float4 c1b = make_float4(0.f, 0.f, 0.f, 0.f);
#pragma unroll
    for (int j = 1; j <= 5; j++) {
        int bj = __shfl_sync(FULL, bk, base + j);
        int ij = __shfl_sync(FULL, id, base + j);
        acc_prod(t4[bj * 8 + sub], f4[ij * 8 + sub], c1a, c1b);
    }

    float sc = rsqrtf(fmaxf((float)g_din[d], 1.f)) *
               rsqrtf(fmaxf((float)g_dout[s], 1.f));
    float m = 0.2f * sc;
    c0a.x *= sc; c0a.y *= sc; c0a.z *= sc; c0a.w *= sc;
    c0b.x *= sc; c0b.y *= sc; c0b.z *= sc; c0b.w *= sc;
    c1a.x *= m;  c1a.y *= m;  c1a.z *= m;  c1a.w *= m;
    c1b.x *= m;  c1b.y *= m;  c1b.z *= m;  c1b.w *= m;

    if (valid) {
        float* p0 = g_acc + d * DD + sub * 8;   // dims [8*sub .. 8*sub+7]
        red_add_v4(p0,          c0a);
        red_add_v4(p0 + 4,      c0b);
        red_add_v4(p0 + D,      c1a);
        red_add_v4(p0 + D + 4,  c1b);
        if (sub == 0) atomicAdd(&g_accs[d], sc);
    }
}

// ---------------------------------------------------------------------------
// 4) persistent GEMM: out = acc @ W^T + accs*b, fma.f32x2 packed over k-pairs.
//    W staged once per block: Ws[d][k] with k-stride KP (conflict-free LDS.64).
#define KP 130
__global__ void gemm_kernel(const float* __restrict__ aggw,
                            const float* __restrict__ aggb,
                            float* __restrict__ out, int n) {
    __shared__ float Ws[D * KP];     // 33.3 KB
    __shared__ float As[16 * KP];    // 8.3 KB
    __shared__ float Ss[16];
    __shared__ float Bs[D];

    int tid = threadIdx.x;
    for (int idx = tid; idx < D * DD; idx += 256) {
        int dd = idx >> 7;
        int k  = idx & 127;
        Ws[dd * KP + k] = aggw[idx];
    }
    if (tid < D) Bs[tid] = aggb[tid];

    int ntiles = (n + 15) >> 4;
    int w = tid >> 5;
    int l = tid & 31;

    for (int t = blockIdx.x; t < ntiles; t += gridDim.x) {
        int basev = t << 4;
        __syncthreads();
        // stage 16 acc rows (8B-aligned stores; row stride KP*4 = 520B)
        for (int idx = tid; idx < 16 * 32; idx += 256) {
            int j = idx >> 5;
            int c = idx & 31;
            int node = basev + j;
            float4 v = make_float4(0.f, 0.f, 0.f, 0.f);
            if (node < n) v = ((const float4*)g_acc)[node * 32 + c];
            float* p = As + j * KP + c * 4;
            *(float2*)p       = make_float2(v.x, v.y);
            *(float2*)(p + 2) = make_float2(v.z, v.w);
        }
        if (tid < 16) Ss[tid] = (basev + tid < n) ? g_accs[basev + tid] : 0.f;
        __syncthreads();

        const float* ar0 = As + (2 * w) * KP;
        const float* ar1 = As + (2 * w + 1) * KP;
        const float* wr0 = Ws + l * KP;
        const float* wr1 = Ws + (l + 32) * KP;

        unsigned long long acc00 = 0ull, acc01 = 0ull, acc10 = 0ull, acc11 = 0ull;
#pragma unroll 8
        for (int k = 0; k < DD; k += 2) {
            unsigned long long a0 = *(const unsigned long long*)(ar0 + k);
            unsigned long long a1 = *(const unsigned long long*)(ar1 + k);
            unsigned long long w0 = *(const unsigned long long*)(wr0 + k);
            unsigned long long w1 = *(const unsigned long long*)(wr1 + k);
            fmaf2(acc00, a0, w0);
            fmaf2(acc01, a0, w1);
            fmaf2(acc10, a1, w0);
            fmaf2(acc11, a1, w1);
        }

        float2 p00 = *(float2*)&acc00;
        float2 p01 = *(float2*)&acc01;
        float2 p10 = *(float2*)&acc10;
        float2 p11 = *(float2*)&acc11;

        int n0 = basev + 2 * w;
        int n1 = n0 + 1;
        if (n0 < n) {
            float ss = Ss[2 * w];
            out[n0 * D + l]      = (p00.x + p00.y) + ss * Bs[l];
            out[n0 * D + l + 32] = (p01.x + p01.y) + ss * Bs[l + 32];
        }
        if (n1 < n) {
            float ss = Ss[2 * w + 1];
            out[n1 * D + l]      = (p10.x + p10.y) + ss * Bs[l];
            out[n1 * D + l + 32] = (p11.x + p11.y) + ss * Bs[l + 32];
        }
    }
}

// ---------------------------------------------------------------------------
extern "C" void kernel_launch(void* const* d_in, const int* in_sizes, int n_in,
                              void* d_out, int out_size) {
    const float*  feat  = (const float*)d_in[0];
    const float2* loc   = (const float2*)d_in[1];
    const float*  embed = (const float*)d_in[2];
    const float*  Gw    = (const float*)d_in[3];
    const float*  aggw  = (const float*)d_in[4];
    const float*  aggb  = (const float*)d_in[5];
    const float*  bnd   = (const float*)d_in[6];
    const int*    src   = (const int*)d_in[7];
    const int*    dst   = (const int*)d_in[8];
    const int*    inter = (const int*)d_in[9];
    float* out = (float*)d_out;

    int n = in_sizes[0] / D;   // 50000
    int e = in_sizes[7];       // 400000

    prep_kernel<<<2048, 256>>>(feat, n);
    table2_kernel<<<(NROWS * D + 255) / 256, 256>>>(embed, Gw);
    degree_kernel<<<(e + 255) / 256, 256>>>(src, dst, e);

    long long threads_needed = (long long)e * 8;
    int blocks = (int)((threads_needed + 255) / 256);
    edge_kernel<<<blocks, 256>>>(loc, bnd, src, dst, inter, e);

    gemm_kernel<<<740, 256>>>(aggw, aggb, out, n);
}